// round 16
// baseline (speedup 1.0000x reference)
#include <cuda_runtime.h>
#include <cuda_fp16.h>
#include <mma.h>
#include <math.h>
#include <stdint.h>

using namespace nvcuda;

// ---------------- problem constants ----------------
#define RESO 56
#define WS   7
#define CDIM 128
#define NHEAD 4
#define HDIM 32
#define HID  512
#define BATCH 32
#define NTOK (BATCH * RESO * RESO)      // 100352
#define NWIN (BATCH * 8 * 8)            // 2048 windows
#define TWIN 49

#define W_QKV_N 49152
#define W_PROJ_N 16384
#define W_W1_N 65536
#define W_W2_N 65536
#define W_TOTAL (W_QKV_N + W_PROJ_N + W_W1_N + W_W2_N)
#define W_BLOCKS ((W_TOTAL + 255) / 256)          // 769
#define LN_BLOCKS ((NTOK * 32) / 256)             // 12544

// ---------------- device scratch ----------------
__device__ __half g_lnh[(size_t)NTOK * CDIM];
__device__ __half g_qkvh[(size_t)NTOK * 3 * CDIM];
__device__ __half g_oh [(size_t)NTOK * CDIM];
__device__ __half g_x2h[(size_t)NTOK * CDIM];
__device__ __half g_h1h[(size_t)NTOK * HID];
__device__ __half g_wTh[W_TOTAL];

__device__ __forceinline__ uint32_t smem_u32(const void* p) {
    uint32_t a;
    asm("{ .reg .u64 t; cvta.to.shared.u64 t, %1; cvt.u32.u64 %0, t; }" : "=r"(a) : "l"(p));
    return a;
}
__device__ __forceinline__ void cp_async16(uint32_t saddr, const void* gaddr) {
    asm volatile("cp.async.ca.shared.global [%0], [%1], 16;" :: "r"(saddr), "l"(gaddr));
}
#define CP_COMMIT() asm volatile("cp.async.commit_group;" ::: "memory")
#define CP_WAIT(n)  asm volatile("cp.async.wait_group %0;" :: "n"(n) : "memory")

__device__ __forceinline__ void store_half4(__half* dst, float a, float b, float c, float d) {
    __half2 h01 = __floats2half2_rn(a, b);
    __half2 h23 = __floats2half2_rn(c, d);
    uint2 u;
    u.x = *(uint32_t*)&h01;
    u.y = *(uint32_t*)&h23;
    *(uint2*)dst = u;
}

// ---------------- fused prep: weight->half + LN1->half ----------------
__global__ void prep_kernel(const float* __restrict__ w0, const float* __restrict__ w1,
                            const float* __restrict__ w2, const float* __restrict__ w3,
                            __half* __restrict__ WT,
                            const float* __restrict__ x, const float* __restrict__ g,
                            const float* __restrict__ b, __half* __restrict__ out)
{
    if (blockIdx.x < W_BLOCKS) {
        int idx = blockIdx.x * 256 + threadIdx.x;
        if (idx >= W_TOTAL) return;
        float v;
        if (idx < W_QKV_N)                          v = w0[idx];
        else if (idx < W_QKV_N + W_PROJ_N)          v = w1[idx - W_QKV_N];
        else if (idx < W_QKV_N + W_PROJ_N + W_W1_N) v = w2[idx - W_QKV_N - W_PROJ_N];
        else                                        v = w3[idx - W_QKV_N - W_PROJ_N - W_W1_N];
        WT[idx] = __float2half_rn(v);
        return;
    }
    int gwarp = ((blockIdx.x - W_BLOCKS) * 256 + threadIdx.x) >> 5;
    int lane  = threadIdx.x & 31;
    if (gwarp >= NTOK) return;
    float4 v = ((const float4*)(x + (size_t)gwarp * CDIM))[lane];
    float s  = v.x + v.y + v.z + v.w;
    float ss = v.x*v.x + v.y*v.y + v.z*v.z + v.w*v.w;
    #pragma unroll
    for (int off = 16; off; off >>= 1) {
        s  += __shfl_xor_sync(0xffffffffu, s,  off);
        ss += __shfl_xor_sync(0xffffffffu, ss, off);
    }
    float mean = s * (1.0f / CDIM);
    float var  = ss * (1.0f / CDIM) - mean * mean;
    float rstd = rsqrtf(var + 1e-5f);
    float4 gg = ((const float4*)g)[lane];
    float4 bb = ((const float4*)b)[lane];
    store_half4(out + (size_t)gwarp * CDIM + lane * 4,
                (v.x - mean) * rstd * gg.x + bb.x,
                (v.y - mean) * rstd * gg.y + bb.y,
                (v.z - mean) * rstd * gg.z + bb.z,
                (v.w - mean) * rstd * gg.w + bb.w);
}

// ---------------- fp16 WMMA GEMM: K-chunks of 64 (R15 proven) --------------
enum { EPI_BIAS = 0, EPI_GELU = 2, EPI_RES_LN2 = 3, EPI_BIAS_RESH = 4 };

#define AH_STRIDE 72
#define BH_STRIDE 136
#define C_STRIDE  132
#define ABUFH (128 * AH_STRIDE * 2)     // 18432 B
#define BBUFH (64 * BH_STRIDE * 2)      // 17408 B
#define SMEM_BYTES (2 * (ABUFH + BBUFH))// 71680 B

template <int EPI>
__global__ void __launch_bounds__(256, 2)
tc_gemm(const __half* __restrict__ A, const __half* __restrict__ B,
        const float* __restrict__ bias, const float* __restrict__ res,
        const __half* __restrict__ resh,
        float* __restrict__ Cf, __half* __restrict__ Ch, int N, int K,
        const float* __restrict__ lng, const float* __restrict__ lnb,
        __half* __restrict__ C2)
{
    extern __shared__ char smem[];
    uint32_t sbase = smem_u32(smem);
    const int tid = threadIdx.x;
    const int wid = tid >> 5;
    const int warpM = wid & 1;
    const int warpN = wid >> 1;
    const int M0 = blockIdx.y * 128;
    const int N0 = blockIdx.x * 128;

    const __half* Abase = A + (size_t)M0 * K;
    const __half* Bbase = B + N0;
    const int nchunk = K >> 6;

    wmma::fragment<wmma::accumulator, 16, 16, 16, float> acc[4][2];
    #pragma unroll
    for (int i = 0; i < 4; i++)
        #pragma unroll
        for (int j = 0; j < 2; j++) wmma::fill_fragment(acc[i][j], 0.0f);

    auto load_chunk = [&](int c) {
        int buf = c & 1;
        uint32_t sa = sbase + buf * ABUFH;
        uint32_t sb = sbase + 2 * ABUFH + buf * BBUFH;
        int k0 = c << 6;
        #pragma unroll
        for (int q = 0; q < 4; q++) {
            int e = tid + q * 256;
            int row = e >> 3, c8 = (e & 7) * 8;
            cp_async16(sa + (row * AH_STRIDE + c8) * 2,
                       Abase + (size_t)row * K + k0 + c8);
        }
        #pragma unroll
        for (int q = 0; q < 4; q++) {
            int e = tid + q * 256;
            int row = e >> 4, c8 = (e & 15) * 8;
            cp_async16(sb + (row * BH_STRIDE + c8) * 2,
                       Bbase + (size_t)(k0 + row) * N + c8);
        }
    };

    load_chunk(0);
    CP_COMMIT();

    for (int c = 0; c < nchunk; c++) {
        if (c + 1 < nchunk) {
            load_chunk(c + 1);
            CP_COMMIT();
            CP_WAIT(1);
        } else {
            CP_WAIT(0);
        }
        __syncthreads();

        int buf = c & 1;
        const __half* As = (const __half*)(smem + buf * ABUFH);
        const __half* Bs = (const __half*)(smem + 2 * ABUFH + buf * BBUFH);
        #pragma unroll
        for (int ks = 0; ks < 4; ks++) {
            wmma::fragment<wmma::matrix_a, 16, 16, 16, __half, wmma::row_major> af[4];
            wmma::fragment<wmma::matrix_b, 16, 16, 16, __half, wmma::row_major> bf[2];
            #pragma unroll
            for (int i = 0; i < 4; i++)
                wmma::load_matrix_sync(af[i],
                    As + (warpM * 64 + i * 16) * AH_STRIDE + ks * 16, AH_STRIDE);
            #pragma unroll
            for (int j = 0; j < 2; j++)
                wmma::load_matrix_sync(bf[j],
                    Bs + (ks * 16) * BH_STRIDE + warpN * 32 + j * 16, BH_STRIDE);
            #pragma unroll
            for (int i = 0; i < 4; i++)
                #pragma unroll
                for (int j = 0; j < 2; j++)
                    wmma::mma_sync(acc[i][j], af[i], bf[j], acc[i][j]);
        }
        __syncthreads();
    }

    float* Cs = (float*)smem;
    #pragma unroll
    for (int i = 0; i < 4; i++)
        #pragma unroll
        for (int j = 0; j < 2; j++)
            wmma::store_matrix_sync(
                Cs + (warpM * 64 + i * 16) * C_STRIDE + warpN * 32 + j * 16,
                acc[i][j], C_STRIDE, wmma::mem_row_major);
    __syncthreads();

    #pragma unroll
    for (int e0 = 0; e0 < 16; e0++) {
        int e = tid + e0 * 256;
        int row = e >> 5;
        int c4  = (e & 31) * 4;
        size_t roff = (size_t)(M0 + row) * N + N0 + c4;
        float rv[4] = {0, 0, 0, 0};
        if (EPI == EPI_BIAS_RESH) {
            uint2 ru = *(const uint2*)(resh + roff);
            float2 r0 = __half22float2(*(__half2*)&ru.x);
            float2 r1 = __half22float2(*(__half2*)&ru.y);
            rv[0] = r0.x; rv[1] = r0.y; rv[2] = r1.x; rv[3] = r1.y;
        }
        float v[4];
        #pragma unroll
        for (int q = 0; q < 4; q++) {
            float t = Cs[row * C_STRIDE + c4 + q] + __ldg(bias + N0 + c4 + q);
            if (EPI == EPI_RES_LN2) t += res[roff + q];
            if (EPI == EPI_BIAS_RESH) t += rv[q];
            if (EPI == EPI_GELU)
                t = 0.5f * t * (1.0f + erff(t * 0.70710678118654752f));
            v[q] = t;
        }
        if (EPI == EPI_BIAS_RESH) {
            *(float4*)(Cf + roff) = *(float4*)v;
        } else {
            store_half4(Ch + roff, v[0], v[1], v[2], v[3]);
        }
        if (EPI == EPI_RES_LN2) {
            float s  = v[0] + v[1] + v[2] + v[3];
            float ss = v[0]*v[0] + v[1]*v[1] + v[2]*v[2] + v[3]*v[3];
            #pragma unroll
            for (int off = 16; off; off >>= 1) {
                s  += __shfl_xor_sync(0xffffffffu, s,  off);
                ss += __shfl_xor_sync(0xffffffffu, ss, off);
            }
            float mean = s * (1.0f / CDIM);
            float var  = ss * (1.0f / CDIM) - mean * mean;
            float rstd = rsqrtf(var + 1e-5f);
            store_half4(C2 + roff,
                        (v[0] - mean) * rstd * __ldg(lng + c4 + 0) + __ldg(lnb + c4 + 0),
                        (v[1] - mean) * rstd * __ldg(lng + c4 + 1) + __ldg(lnb + c4 + 1),
                        (v[2] - mean) * rstd * __ldg(lng + c4 + 2) + __ldg(lnb + c4 + 2),
                        (v[3] - mean) * rstd * __ldg(lng + c4 + 3) + __ldg(lnb + c4 + 3));
        }
    }
}

// ---------------- attention: one block per (window, head-pair) -------------
// 8 warps: 4 per head (heads processed concurrently, no head loop).
// smem (bytes):
//   tok: 0..256
//   qh : 256    (2 heads x 64 x 40 halves = 10240)
//   kh : 10496  (10240)
//   vh : 20736  (10240)
//   Ss : 30976  (2 x 64 x 68 fp32 = 34816)
//   Ph : 65792  (2 x 64 x 72 half = 18432)
#define ATT_SMEM 84224

__global__ void __launch_bounds__(256)
attn_kernel(const __half* __restrict__ qkv, __half* __restrict__ o)
{
    extern __shared__ char smc[];
    int*    tok = (int*)smc;
    __half* qh  = (__half*)(smc + 256);
    __half* kh  = qh + 5120;
    __half* vh  = qh + 10240;
    float*  Ss  = (float*)(smc + 30976);
    __half* Ph  = (__half*)(smc + 65792);

    int blk = blockIdx.x;
    int w = blk >> 1, hp = blk & 1;     // head pair: heads hp*2, hp*2+1
    int bimg = w >> 6, win = w & 63;
    int wr = win >> 3, wc = win & 7;
    int tid = threadIdx.x, wid = tid >> 5, lane = tid & 31;

    if (tid < TWIN) {
        int r = tid / WS, c = tid - r * WS;
        tok[tid] = bimg * (RESO * RESO) + (wr * WS + r) * RESO + (wc * WS + c);
    }
    // zero pad rows 49..63 of q/k/v (2 heads): 3*2*15*5 = 450 uint4
    for (int i = tid; i < 450; i += 256) {
        int tensor = i / 150;
        int hh = (i / 75) & 1;
        int rr = (i / 5) % 15;
        int u = i % 5;
        __half* base = (tensor == 0) ? qh : (tensor == 1) ? kh : vh;
        *(uint4*)(base + hh * 2560 + (49 + rr) * 40 + u * 8) = make_uint4(0, 0, 0, 0);
    }
    // zero Ph pad rows 49..63 (2 heads): 2*15*9 = 270 uint4
    for (int i = tid; i < 270; i += 256) {
        int hh = i / 135;
        int rr = (i % 135) / 9;
        int u = i % 9;
        *(uint4*)(Ph + hh * 4608 + (49 + rr) * 72 + u * 8) = make_uint4(0, 0, 0, 0);
    }
    __syncthreads();

    // gather: 49 tokens x 3 tensors x 2 heads x 4 uint4 = 1176
    for (int i = tid; i < TWIN * 24; i += 256) {
        int t = i / 24, c = i - t * 24;
        int tensor = c >> 3, hh = (c >> 2) & 1, u = c & 3;
        uint4 hv = *(const uint4*)(qkv + (size_t)tok[t] * 384
                                   + tensor * 128 + (hp * 2 + hh) * 32 + u * 8);
        __half* base = (tensor == 0) ? qh : (tensor == 1) ? kh : vh;
        *(uint4*)(base + hh * 2560 + t * 40 + u * 8) = hv;
    }
    __syncthreads();

    const float scale = 0.17677669529663687f;
    const int h  = wid >> 2;            // 0..1 (head within pair)
    const int wm = wid & 3;             // 16-row slice
    const __half* q = qh + h * 2560;
    const __half* k = kh + h * 2560;
    const __half* v = vh + h * 2560;
    float*  Ssh = Ss + h * 4352;        // 64 x 68
    __half* Phh = Ph + h * 4608;        // 64 x 72

    // S = Q @ K^T (64x64x32): each warp 16 rows x 64 cols = 8 MMAs
    {
        wmma::fragment<wmma::accumulator, 16, 16, 16, float> sa[4];
        #pragma unroll
        for (int j = 0; j < 4; j++) wmma::fill_fragment(sa[j], 0.0f);
        #pragma unroll
        for (int kt = 0; kt < 2; kt++) {
            wmma::fragment<wmma::matrix_a, 16, 16, 16, __half, wmma::row_major> af;
            wmma::load_matrix_sync(af, q + (wm * 16) * 40 + kt * 16, 40);
            #pragma unroll
            for (int j = 0; j < 4; j++) {
                wmma::fragment<wmma::matrix_b, 16, 16, 16, __half, wmma::col_major> bf;
                wmma::load_matrix_sync(bf, k + (j * 16) * 40 + kt * 16, 40);
                wmma::mma_sync(sa[j], af, bf, sa[j]);
            }
        }
        #pragma unroll
        for (int j = 0; j < 4; j++)
            wmma::store_matrix_sync(Ssh + (wm * 16) * 68 + j * 16, sa[j], 68,
                                    wmma::mem_row_major);
    }
    __syncthreads();

    // fused scale + softmax + half conversion -> Ph
    for (int row = wm; row < TWIN; row += 4) {
        float v0 = Ssh[row * 68 + lane] * scale;
        float v1 = (lane + 32 < TWIN) ? Ssh[row * 68 + lane + 32] * scale : -3.4e38f;
        float m = fmaxf(v0, v1);
        #pragma unroll
        for (int off = 16; off; off >>= 1)
            m = fmaxf(m, __shfl_xor_sync(0xffffffffu, m, off));
        float e0 = __expf(v0 - m);
        float e1 = (lane + 32 < TWIN) ? __expf(v1 - m) : 0.0f;
        float s = e0 + e1;
        #pragma unroll
        for (int off = 16; off; off >>= 1)
            s += __shfl_xor_sync(0xffffffffu, s, off);
        float inv = 1.0f / s;
        Phh[row * 72 + lane]      = __float2half_rn(e0 * inv);
        Phh[row * 72 + lane + 32] = __float2half_rn(e1 * inv);
    }
    __syncthreads();

    // O = P @ V (64x32x64): each warp 16 rows x 32 cols = 8 MMAs
    {
        wmma::fragment<wmma::accumulator, 16, 16, 16, float> oa[2];
        wmma::fill_fragment(oa[0], 0.0f);
        wmma::fill_fragment(oa[1], 0.0f);
        #pragma unroll
        for (int kt = 0; kt < 4; kt++) {
            wmma::fragment<wmma::matrix_a, 16, 16, 16, __half, wmma::row_major> pf;
            wmma::load_matrix_sync(pf, Phh + (wm * 16) * 72 + kt * 16, 72);
            #pragma unroll
            for (int j = 0; j < 2; j++) {
                wmma::fragment<wmma::matrix_b, 16, 16, 16, __half, wmma::row_major> vf;
                wmma::load_matrix_sync(vf, v + (kt * 16) * 40 + j * 16, 40);
                wmma::mma_sync(oa[j], pf, vf, oa[j]);
            }
        }
        #pragma unroll
        for (int j = 0; j < 2; j++)
            wmma::store_matrix_sync(Ssh + (wm * 16) * 68 + j * 16, oa[j], 68,
                                    wmma::mem_row_major);
    }
    __syncthreads();

    // scatter (2 heads x 49 rows x 16 half2)
    for (int i = tid; i < 2 * TWIN * 16; i += 256) {
        int hh = i / 784;
        int rem = i - hh * 784;
        int r = rem >> 4, d = (rem & 15) * 2;
        const float* src = Ss + hh * 4352 + r * 68 + d;
        __half2 p = __floats2half2_rn(src[0], src[1]);
        *(__half2*)(o + (size_t)tok[r] * CDIM + (hp * 2 + hh) * HDIM + d) = p;
    }
}

// ---------------- launch ----------------
extern "C" void kernel_launch(void* const* d_in, const int* in_sizes, int n_in,
                              void* d_out, int out_size)
{
    const float* x      = (const float*)d_in[0];
    const float* ln1_g  = (const float*)d_in[1];
    const float* ln1_b  = (const float*)d_in[2];
    const float* qkv_w  = (const float*)d_in[3];
    const float* qkv_b  = (const float*)d_in[4];
    const float* proj_w = (const float*)d_in[5];
    const float* proj_b = (const float*)d_in[6];
    const float* ln2_g  = (const float*)d_in[7];
    const float* ln2_b  = (const float*)d_in[8];
    const float* mlp_w1 = (const float*)d_in[9];
    const float* mlp_b1 = (const float*)d_in[10];
    const float* mlp_w2 = (const float*)d_in[11];
    const float* mlp_b2 = (const float*)d_in[12];
    float* out = (float*)d_out;

    __half *p_lnh, *p_qkvh, *p_oh, *p_x2h, *p_h1h, *p_wTh;
    cudaGetSymbolAddress((void**)&p_lnh,  g_lnh);
    cudaGetSymbolAddress((void**)&p_qkvh, g_qkvh);
    cudaGetSymbolAddress((void**)&p_oh,   g_oh);
    cudaGetSymbolAddress((void**)&p_x2h,  g_x2h);
    cudaGetSymbolAddress((void**)&p_h1h,  g_h1h);
    cudaGetSymbolAddress((void**)&p_wTh,  g_wTh);
    __half* wt_qkv  = p_wTh;
    __half* wt_proj = p_wTh + W_QKV_N;
    __half* wt_w1   = p_wTh + W_QKV_N + W_PROJ_N;
    __half* wt_w2   = p_wTh + W_QKV_N + W_PROJ_N + W_W1_N;

    cudaFuncSetAttribute(tc_gemm<EPI_BIAS>,      cudaFuncAttributeMaxDynamicSharedMemorySize, SMEM_BYTES);
    cudaFuncSetAttribute(tc_gemm<EPI_GELU>,      cudaFuncAttributeMaxDynamicSharedMemorySize, SMEM_BYTES);
    cudaFuncSetAttribute(tc_gemm<EPI_RES_LN2>,   cudaFuncAttributeMaxDynamicSharedMemorySize, SMEM_BYTES);
    cudaFuncSetAttribute(tc_gemm<EPI_BIAS_RESH>, cudaFuncAttributeMaxDynamicSharedMemorySize, SMEM_BYTES);
    cudaFuncSetAttribute(attn_kernel,            cudaFuncAttributeMaxDynamicSharedMemorySize, ATT_SMEM);

    const int MT = NTOK / 128;  // 784

    // 0. fused prep: weight->half + LN1->half
    prep_kernel<<<W_BLOCKS + LN_BLOCKS, 256>>>(qkv_w, proj_w, mlp_w1, mlp_w2, p_wTh,
                                               x, ln1_g, ln1_b, p_lnh);
    // 1. QKV = ln1 @ qkv_w + qkv_b  -> half
    tc_gemm<EPI_BIAS><<<dim3(3, MT), 256, SMEM_BYTES>>>(
        p_lnh, wt_qkv, qkv_b, nullptr, nullptr, nullptr, p_qkvh, 3 * CDIM, CDIM,
        nullptr, nullptr, nullptr);
    // 2. attention (one block per window-headpair)
    attn_kernel<<<NWIN * 2, 256, ATT_SMEM>>>(p_qkvh, p_oh);
    // 3. x2 = x + proj(o) -> half ; fused LN2 -> half
    tc_gemm<EPI_RES_LN2><<<dim3(1, MT), 256, SMEM_BYTES>>>(
        p_oh, wt_proj, proj_b, x, nullptr, nullptr, p_x2h, CDIM, CDIM,
        ln2_g, ln2_b, p_lnh);
    // 4. h1 = gelu(ln2 @ w1 + b1) -> half
    tc_gemm<EPI_GELU><<<dim3(4, MT), 256, SMEM_BYTES>>>(
        p_lnh, wt_w1, mlp_b1, nullptr, nullptr, nullptr, p_h1h, HID, CDIM,
        nullptr, nullptr, nullptr);
    // 5. out = x2 + h1 @ w2 + b2  (fp32 out, half residual)
    tc_gemm<EPI_BIAS_RESH><<<dim3(1, MT), 256, SMEM_BYTES>>>(
        p_h1h, wt_w2, mlp_b2, nullptr, p_x2h, out, nullptr, CDIM, HID,
        nullptr, nullptr, nullptr);
}